// round 8
// baseline (speedup 1.0000x reference)
#include <cuda_runtime.h>
#include <cuda_fp16.h>
#include <math.h>
#include <float.h>

#define NROWS 200000
#define NBAGS 25000
#define DIM   690
#define NREL  53
#define KPAD  704
#define NPAD  64           // P row stride (cols 56..63 unused)
#define NB    56           // computed cols (7 n-tiles)
#define BM    128
#define KC    32
#define NCHUNK 22          // KPAD / KC
#define PF    36           // fp32 A stage pitch (floats)
#define BPITCH 40          // fp16 B pitch (80B rows, LDSM conflict-free)
#define NSTAGE 3
#define A_STAGE_BYTES (BM * PF * 4)            // 18432
#define B_HALF_BYTES  (NPAD * BPITCH * 2)      // 5120
#define B_STAGE_BYTES (2 * B_HALF_BYTES)       // 10240 (hi then lo)
#define SMEM_B_OFF    (NSTAGE * A_STAGE_BYTES) // 55296
#define SMEM_TOTAL    (SMEM_B_OFF + NSTAGE * B_STAGE_BYTES)  // 86016
#define WCAP  128

// ---------------- scratch (device globals: allocation-free) ----------------
__device__ __align__(16) float g_P[(size_t)NROWS * NPAD];       // 51.2 MB
__device__ __align__(16) __half g_Bhi[NPAD * KPAD];
__device__ __align__(16) __half g_Blo[NPAD * KPAD];
__device__ float g_wglob[NROWS];

// ---------------- K0: build fp16 hi/lo B = rel (padded, [n][k]) ------------
__global__ void k_prep(const float* __restrict__ rel) {
    int idx = blockIdx.x * blockDim.x + threadIdx.x;
    if (idx >= NPAD * KPAD) return;
    int n = idx / KPAD, k = idx % KPAD;
    float v = (n < NREL && k < DIM) ? rel[n * DIM + k] : 0.f;
    __half hi = __float2half(v);
    g_Bhi[idx] = hi;
    g_Blo[idx] = __float2half(v - __half2float(hi));
}

// ---------------- PTX helpers ----------------
__device__ __forceinline__ void mma_f16(float* c, const unsigned* a, const unsigned* b) {
    asm volatile(
        "mma.sync.aligned.m16n8k16.row.col.f32.f16.f16.f32 "
        "{%0,%1,%2,%3}, {%4,%5,%6,%7}, {%8,%9}, {%0,%1,%2,%3};"
        : "+f"(c[0]), "+f"(c[1]), "+f"(c[2]), "+f"(c[3])
        : "r"(a[0]), "r"(a[1]), "r"(a[2]), "r"(a[3]), "r"(b[0]), "r"(b[1]));
}
__device__ __forceinline__ void ldsm2(unsigned* r, unsigned addr) {
    asm volatile("ldmatrix.sync.aligned.m8n8.x2.shared.b16 {%0,%1}, [%2];"
                 : "=r"(r[0]), "=r"(r[1]) : "r"(addr));
}
__device__ __forceinline__ void cp8(unsigned dst, const void* src, int bytes) {
    asm volatile("cp.async.ca.shared.global [%0], [%1], 8, %2;"
                 :: "r"(dst), "l"(src), "r"(bytes));
}
__device__ __forceinline__ void cp16(unsigned dst, const void* src) {
    asm volatile("cp.async.cg.shared.global [%0], [%1], 16;"
                 :: "r"(dst), "l"(src));
}
__device__ __forceinline__ void cp_commit() {
    asm volatile("cp.async.commit_group;" ::: "memory");
}
__device__ __forceinline__ void cp_wait1() {
    asm volatile("cp.async.wait_group 1;" ::: "memory");
}

// ---------------- K1: P = repre @ rel^T, pipelined fp16 2-term MMA ---------
__global__ __launch_bounds__(256) void k_pgemm(const float* __restrict__ repre) {
    extern __shared__ __align__(16) char smem[];
    unsigned sbase = (unsigned)__cvta_generic_to_shared(smem);
    float* sF = (float*)smem;

    int row0 = blockIdx.x * BM;
    int tid = threadIdx.x, wid = tid >> 5, lane = tid & 31;

    // ---- A cp geometry ----
    int ar  = tid >> 1;
    int asb = (tid & 1) * 8;
    int gr  = row0 + ar;
    bool arow_ok = gr < NROWS;
    const float* asrc_row = repre + (size_t)(arow_ok ? gr : (NROWS - 1)) * DIM;
    unsigned adst_row = sbase + (unsigned)(ar * PF * 4);

    // ---- B cp geometry: rows 0..55 only ----
    int bn = tid >> 2, bs = tid & 3;
    bool b_ok = bn < NB;
    unsigned bdst = sbase + SMEM_B_OFF + (unsigned)((bn * BPITCH + bs * 8) * 2);

    // ---- compute geometry ----
    int wrow = wid * 16;
    int g = lane >> 2, th = lane & 3;
    int brow = lane & 7, bcolsel = lane & 8;

    float acc[7][4];
#pragma unroll
    for (int j = 0; j < 7; j++)
#pragma unroll
        for (int q = 0; q < 4; q++) acc[j][q] = 0.f;

    auto issue = [&](int cs) {
        int st = cs % NSTAGE;
        int k0 = cs * KC;
        unsigned da = adst_row + (unsigned)(st * A_STAGE_BYTES) + (unsigned)(asb * 8);
#pragma unroll
        for (int i = 0; i < 8; i++) {
            int kf = k0 + (asb + i) * 2;
            int bytes = arow_ok ? max(0, min(8, (DIM - kf) * 4)) : 0;
            const float* sp = asrc_row + (bytes > 0 ? kf : 0);
            cp8(da + i * 8, sp, bytes);
        }
        if (b_ok) {
            unsigned db = bdst + (unsigned)(st * B_STAGE_BYTES);
            int boffg = bn * KPAD + k0 + bs * 8;
            cp16(db, g_Bhi + boffg);
            cp16(db + B_HALF_BYTES, g_Blo + boffg);
        }
    };

    issue(0); cp_commit();
    issue(1); cp_commit();

    for (int c = 0; c < NCHUNK; c++) {
        cp_wait1();
        __syncthreads();
        int st = c % NSTAGE;
        const float* A = sF + st * (BM * PF);
        unsigned sBst = sbase + SMEM_B_OFF + (unsigned)(st * B_STAGE_BYTES);

        // ---- build single fp16 A fragments in regs (both k16 steps) ----
        unsigned ah[2][4];
#pragma unroll
        for (int ks2 = 0; ks2 < 2; ks2++) {
#pragma unroll
            for (int q = 0; q < 4; q++) {
                int r   = wrow + g + (q & 1) * 8;
                int col = ks2 * 16 + th * 2 + (q >> 1) * 8;
                float2 v = *(const float2*)(A + r * PF + col);
                asm("cvt.rn.f16x2.f32 %0, %1, %2;"
                    : "=r"(ah[ks2][q]) : "f"(v.y), "f"(v.x));
            }
        }

        // ---- MMA over 7 n-tiles x 2 k-steps x 2 terms ----
#pragma unroll
        for (int j = 0; j < 7; j++) {
            unsigned bb = sBst + (unsigned)(((j * 8 + brow) * BPITCH + bcolsel) * 2);
#pragma unroll
            for (int ks2 = 0; ks2 < 2; ks2++) {
                unsigned bhi[2], blo[2];
                ldsm2(bhi, bb + ks2 * 32);
                ldsm2(blo, bb + B_HALF_BYTES + ks2 * 32);
                mma_f16(acc[j], ah[ks2], bhi);
                mma_f16(acc[j], ah[ks2], blo);
            }
        }
        __syncthreads();
        if (c + NSTAGE - 1 < NCHUNK) issue(c + NSTAGE - 1);
        cp_commit();
    }

    // ---- epilogue: write P (56 cols) ----
    int r1 = row0 + wrow + g;
    int r2 = r1 + 8;
#pragma unroll
    for (int j = 0; j < 7; j++) {
        int col = j * 8 + th * 2;
        if (r1 < NROWS)
            *(float2*)&g_P[(size_t)r1 * NPAD + col] = make_float2(acc[j][0], acc[j][1]);
        if (r2 < NROWS)
            *(float2*)&g_P[(size_t)r2 * NPAD + col] = make_float2(acc[j][2], acc[j][3]);
    }
}

// ---------------- K2: per-bag softmax + combine over P ---------------------
__global__ __launch_bounds__(256) void k_bags(const int* __restrict__ scope,
                                              const int* __restrict__ labels,
                                              const float* __restrict__ bias,
                                              float* __restrict__ out) {
    __shared__ float wbuf[8][WCAP];
    int wid = threadIdx.x >> 5, lane = threadIdx.x & 31;
    int bag = blockIdx.x * 8 + wid;
    if (bag >= NBAGS) return;
    int s = scope[2 * bag];
    int e = scope[2 * bag + 1];
    int c = e - s;
    float* w = (c <= WCAP) ? wbuf[wid] : (g_wglob + s);

    float m = -FLT_MAX;
    for (int i = lane; i < c; i += 32) {
        int gi = s + i;
        float lg = g_P[(size_t)gi * NPAD + labels[gi]];
        w[i] = lg;
        m = fmaxf(m, lg);
    }
#pragma unroll
    for (int o = 16; o; o >>= 1) m = fmaxf(m, __shfl_xor_sync(0xffffffffu, m, o));

    float sum = 0.f;
    for (int i = lane; i < c; i += 32) {
        float ev = __expf(w[i] - m);
        w[i] = ev;
        sum += ev;
    }
#pragma unroll
    for (int o = 16; o; o >>= 1) sum += __shfl_xor_sync(0xffffffffu, sum, o);
    float inv = 1.f / sum;
    __syncwarp();

    int col = lane * 2;
    float2 o2 = make_float2(0.f, 0.f);
    const float* pbase = g_P + (size_t)s * NPAD + col;
#pragma unroll 4
    for (int i = 0; i < c; i++) {
        float wi = w[i] * inv;
        float2 p2 = *(const float2*)(pbase + (size_t)i * NPAD);
        o2.x = fmaf(wi, p2.x, o2.x);
        o2.y = fmaf(wi, p2.y, o2.y);
    }
    if (col < NREL)     out[(size_t)bag * NREL + col]     = o2.x + bias[col];
    if (col + 1 < NREL) out[(size_t)bag * NREL + col + 1] = o2.y + bias[col + 1];
}

// ---------------- launch ----------------
extern "C" void kernel_launch(void* const* d_in, const int* in_sizes, int n_in,
                              void* d_out, int out_size) {
    const float* repre  = (const float*)d_in[0];   // [N, D]
    const float* rel    = (const float*)d_in[1];   // [R, D]
    const float* bias   = (const float*)d_in[2];   // [R]
    const int* scope    = (const int*)d_in[3];     // [NBAGS, 2] int32
    const int* labels   = (const int*)d_in[4];     // [N]        int32
    float* out = (float*)d_out;                    // [NBAGS, R]

    (void)in_sizes; (void)n_in; (void)out_size;

    cudaFuncSetAttribute(k_pgemm, cudaFuncAttributeMaxDynamicSharedMemorySize,
                         SMEM_TOTAL);

    k_prep<<<(NPAD * KPAD + 255) / 256, 256>>>(rel);
    k_pgemm<<<(NROWS + BM - 1) / BM, 256, SMEM_TOTAL>>>(repre);
    k_bags<<<(NBAGS + 7) / 8, 256>>>(scope, labels, bias, out);
}